// round 11
// baseline (speedup 1.0000x reference)
#include <cuda_runtime.h>
#include <cuda_fp16.h>
#include <mma.h>
#include <cstdint>
#include <math.h>

using namespace nvcuda;

// Problem constants
#define TSTEPS 512
#define BATCH  512
#define IDIM   128
#define HDIM   512
#define KACT   640   // reordered: cols [0,512)=h, [512,640)=inp

// Partitioning: 8 batch-groups x 16 CTAs = 128 CTAs (1 per SM, one wave)
#define NGROUPS 8
#define GCTAS   16
#define NCTA    (NGROUPS*GCTAS)
#define MB      64
#define HS      32
#define NTHREADS 256   // 8 warps: 2 warp-rows x 4 warp-cols (32x32 tiles)

// SMEM padding / tiling
#define WPAD 648      // weight row stride (halfs)
#define GPAD 132      // gates/pbuf staging row stride (floats)
#define APAD 136      // A-stage row stride (halfs)
#define FPAD 40       // Hloc / FCsm row stride (halfs)
#define CHUNK 128     // K columns per staged chunk
#define NCHUNK 5      // 640 / 128
#define HCHUNK 4      // chunks [0,4) = h region [0,512); chunk 4 = inp [512,640)

// SMEM layout (bytes):
//  Wsm  128*WPAD*2 = 165888  @ 0
//  R    max(Ast 2*64*APAD*2=34816, gsm/pbuf 64*GPAD*4=33792) = 34816 @ 165888
//  Hloc 64*FPAD*2  = 5120    @ 200704
//  FCsm 128*FPAD*2 = 10240   @ 205824
//  bsm  128*4      = 512     @ 216064
//  fcbs 8*4        = 32      @ 216576
#define SMEM_BYTES 216704

// Global state
__device__ __align__(16) __half g_act[2][BATCH][KACT];      // [parity][row][col]
// fc partials, blocked: [gid][dst_rk][src_rk][64][8] -> reduce reads contiguous
__device__ __align__(16) float g_fcpart[NGROUPS*GCTAS*GCTAS*MB*8];
__device__ unsigned g_bar[NGROUPS];                          // monotonic counters

// ---------------- barriers (release-atomic + acquire-fence spin) ----------------
__device__ __forceinline__ void bar_arrive(const unsigned* barp) {
    if (threadIdx.x == 0) {
        asm volatile("red.release.gpu.global.add.u32 [%0], %1;"
                     :: "l"(barp), "r"(1u) : "memory");
    }
}
__device__ __forceinline__ void bar_wait(const unsigned* barp, unsigned target) {
    if (threadIdx.x == 0) {
        unsigned v;
        do {
            asm volatile("ld.relaxed.gpu.global.u32 %0, [%1];" : "=r"(v) : "l"(barp));
        } while (v < target);
        asm volatile("fence.acq_rel.gpu;" ::: "memory");
    }
    __syncthreads();
}

__device__ __forceinline__ uint4 ldcg4(const void* p) {
    return __ldcg(reinterpret_cast<const uint4*>(p));
}

// Overflow-safe fast sigmoid/tanh (EX2+RCP MUFU path, rel err ~2^-21)
__device__ __forceinline__ float fsigmoid(float z) {
    float e = __expf(-fabsf(z));
    float num = (z >= 0.f) ? 1.f : e;
    return __fdividef(num, 1.f + e);
}
__device__ __forceinline__ float ftanh_(float z) {
    float e = __expf(-2.f * fabsf(z));
    float r = __fdividef(1.f - e, 1.f + e);
    return (z >= 0.f) ? r : -r;
}

// Staged-chunk MMA over chunks [c_begin, c_end). Accumulates act @ W^T.
// 8 warps: warp (wr,wc) owns rows [wr*32,+32) x gate cols [wc*32,+32).
// Staging per chunk: 64 rows x 128 halves; thread = 4 uint4 (lrow=tid>>2, lseg=tid&3).
__device__ __forceinline__ void mma_chunks(
    wmma::fragment<wmma::accumulator, 16, 16, 16, float> (&acc)[2][2],
    const __half* __restrict__ gact_p,
    __half* __restrict__ Ast,            // [2 buf][64][APAD]
    const __half* __restrict__ Wsm,
    int row0, int wr, int wc, int lrow, int lseg,
    int c_begin, int c_end)
{
    const __half* src = gact_p + (size_t)(row0 + lrow) * KACT + lseg*32;

    {
        const __half* s = src + c_begin*CHUNK;
        uint4 v0 = ldcg4(s);
        uint4 v1 = ldcg4(s + 8);
        uint4 v2 = ldcg4(s + 16);
        uint4 v3 = ldcg4(s + 24);
        uint4* d = reinterpret_cast<uint4*>(Ast + lrow*APAD + lseg*32);
        d[0] = v0; d[1] = v1; d[2] = v2; d[3] = v3;
    }
    __syncthreads();

    int buf = 0;
    for (int cc = c_begin; cc < c_end; cc++) {
        uint4 p0, p1, p2, p3;
        const bool hn = (cc + 1 < c_end);
        if (hn) {
            const __half* s = src + (cc+1)*CHUNK;
            p0 = ldcg4(s);
            p1 = ldcg4(s + 8);
            p2 = ldcg4(s + 16);
            p3 = ldcg4(s + 24);
        }

        const __half* Ab = Ast + buf * (64 * APAD);
        const int kbase = cc * CHUNK;
        #pragma unroll
        for (int kt = 0; kt < 8; kt++) {
            wmma::fragment<wmma::matrix_a, 16, 16, 16, __half, wmma::row_major> af[2];
            #pragma unroll
            for (int i = 0; i < 2; i++)
                wmma::load_matrix_sync(af[i], Ab + (wr*32 + i*16)*APAD + kt*16, APAD);
            #pragma unroll
            for (int j = 0; j < 2; j++) {
                wmma::fragment<wmma::matrix_b, 16, 16, 16, __half, wmma::col_major> bf;
                wmma::load_matrix_sync(bf, Wsm + (wc*32 + j*16)*WPAD + kbase + kt*16, WPAD);
                #pragma unroll
                for (int i = 0; i < 2; i++)
                    wmma::mma_sync(acc[i][j], af[i], bf, acc[i][j]);
            }
        }
        if (hn) {
            buf ^= 1;
            uint4* d = reinterpret_cast<uint4*>(Ast + buf*(64*APAD) + lrow*APAD + lseg*32);
            d[0] = p0; d[1] = p1; d[2] = p2; d[3] = p3;
        }
        __syncthreads();
    }
}

__global__ void __launch_bounds__(NTHREADS, 1)
decoder_kernel(
    const float* __restrict__ x,    const float* __restrict__ h0,
    const float* __restrict__ c0,   const float* __restrict__ W_ih,
    const float* __restrict__ W_hh, const float* __restrict__ b_ih,
    const float* __restrict__ b_hh, const float* __restrict__ fc_W,
    const float* __restrict__ fc_b, float* __restrict__ out)
{
    extern __shared__ unsigned char smem_raw[];
    __half* Wsm  = (__half*)smem_raw;                        // [128][WPAD]
    __half* Ast  = (__half*)(smem_raw + 165888);             // R (aliased)
    float*  gsm  = (float*)(smem_raw + 165888);              // R: [64][GPAD]
    float*  pbuf = (float*)(smem_raw + 165888);              // R: [64][GPAD]
    __half* Hloc = (__half*)(smem_raw + 200704);             // [64][FPAD]
    __half* FCsm = (__half*)(smem_raw + 205824);             // [128][FPAD]
    float*  bsm  = (float*)(smem_raw + 216064);              // [128]
    float*  fcbs = (float*)(smem_raw + 216576);              // [8]

    const int tid  = threadIdx.x;
    const int gid  = blockIdx.x / GCTAS;
    const int rk   = blockIdx.x % GCTAS;
    const int row0 = gid * MB;
    const int hs   = rk * HS;
    const unsigned* barp = &g_bar[gid];

    const int wid = tid >> 5;
    const int wr  = wid >> 2;        // 0..1 : 32 rows each
    const int wc  = wid & 3;         // 0..3 : 32 cols each
    const int lrow = tid >> 2;       // 0..63
    const int lseg = tid & 3;        // 0..3

    // ---------------- init (once) ----------------
    // Wsm: gates, K-reordered (k<512 -> W_hh, k>=512 -> W_ih)
    for (int idx = tid; idx < 128*KACT; idx += NTHREADS) {
        int r = idx / KACT, k = idx - r*KACT;
        int q = r >> 5, j = r & 31;
        int grow = q*HDIM + hs + j;
        float v = (k < HDIM) ? W_hh[grow*HDIM + k] : W_ih[grow*IDIM + (k - HDIM)];
        Wsm[r*WPAD + k] = __float2half_rn(v);
    }
    // FCsm: fc_W K-slice [128 n][32 k]
    for (int idx = tid; idx < 128*HS; idx += NTHREADS) {
        int n = idx / HS, k = idx - n*HS;
        FCsm[n*FPAD + k] = __float2half_rn(fc_W[n*HDIM + hs + k]);
    }
    for (int r = tid; r < 128; r += NTHREADS) {
        int q = r >> 5, j = r & 31;
        bsm[r] = b_ih[q*HDIM + hs + j] + b_hh[q*HDIM + hs + j];
    }
    if (tid < 8) fcbs[tid] = fc_b[rk*8 + tid];

    // cell state in registers: element it -> (m = (tid>>5)+it*8, j = tid&31)
    float cr[8];
    #pragma unroll
    for (int it = 0; it < 8; it++) {
        int m = (tid >> 5) + it*8, j = tid & 31;
        cr[it] = c0[(row0+m)*HDIM + hs + j];
    }

    // seed g_act parity 0
    for (int idx = tid; idx < MB*HS; idx += NTHREADS) {
        int m = idx >> 5, j = idx & 31;
        g_act[0][row0+m][hs+j] = __float2half_rn(h0[(row0+m)*HDIM + hs + j]);
    }
    for (int idx = tid; idx < MB*8; idx += NTHREADS) {
        int m = idx >> 3, ccol = rk*8 + (idx & 7);
        g_act[0][row0+m][HDIM+ccol] =
            __float2half_rn(x[(TSTEPS-1)*BATCH*IDIM + (row0+m)*IDIM + ccol]);
    }

    unsigned tgt = GCTAS;
    bar_arrive(barp);
    bar_wait(barp, tgt);     // seeds visible group-wide

    wmma::fragment<wmma::accumulator, 16, 16, 16, float> acc[2][2];

    // ---------------- prologue: gates(0) ----------------
    {
        #pragma unroll
        for (int i = 0; i < 2; i++)
            #pragma unroll
            for (int j = 0; j < 2; j++)
                wmma::fill_fragment(acc[i][j], 0.0f);
        mma_chunks(acc, &g_act[0][0][0], Ast, Wsm, row0, wr, wc, lrow, lseg, 0, NCHUNK);
        #pragma unroll
        for (int i = 0; i < 2; i++)
            #pragma unroll
            for (int j = 0; j < 2; j++)
                wmma::store_matrix_sync(&gsm[(wr*32 + i*16)*GPAD + wc*32 + j*16],
                                        acc[i][j], GPAD, wmma::mem_row_major);
        __syncthreads();
    }

    float* fcbase = &g_fcpart[(size_t)gid * GCTAS*GCTAS*MB*8];

    // ---------------- 512 sequential steps ----------------
    for (int t = 0; t < TSTEPS; t++) {
        const int pw = (t + 1) & 1;      // parity holding h_{t+1} / inp_{t+1}
        const bool more = (t < TSTEPS - 1);

        // ===== pointwise LSTM: gsm (gates_t) + cr -> h_{t+1} + Hloc =====
        #pragma unroll
        for (int it = 0; it < 8; it++) {
            int m = (tid >> 5) + it*8, j = tid & 31;
            float zi = gsm[m*GPAD +      j] + bsm[     j];
            float zf = gsm[m*GPAD + 32 + j] + bsm[32 + j];
            float zg = gsm[m*GPAD + 64 + j] + bsm[64 + j];
            float zo = gsm[m*GPAD + 96 + j] + bsm[96 + j];
            float ig = fsigmoid(zi);
            float fg = fsigmoid(zf);
            float gg = ftanh_(zg);
            float og = fsigmoid(zo);
            float cn = fg*cr[it] + ig*gg;
            float hn = og * ftanh_(cn);
            cr[it] = cn;
            __half hh = __float2half_rn(hn);
            g_act[pw][row0+m][hs+j] = hh;
            Hloc[m*FPAD + j] = hh;
        }
        __syncthreads();   // Hloc ready; gsm dead (pbuf reusable)

        // ===== fc K-partial: [64x128] = Hloc[64x32] @ FCsm^T (all 8 warps) =====
        {
            wmma::fragment<wmma::accumulator, 16, 16, 16, float> accp[2][2];
            #pragma unroll
            for (int i = 0; i < 2; i++)
                #pragma unroll
                for (int j = 0; j < 2; j++)
                    wmma::fill_fragment(accp[i][j], 0.0f);
            #pragma unroll
            for (int kt = 0; kt < 2; kt++) {
                wmma::fragment<wmma::matrix_a, 16, 16, 16, __half, wmma::row_major> af[2];
                #pragma unroll
                for (int i = 0; i < 2; i++)
                    wmma::load_matrix_sync(af[i], Hloc + (wr*32 + i*16)*FPAD + kt*16, FPAD);
                #pragma unroll
                for (int j = 0; j < 2; j++) {
                    wmma::fragment<wmma::matrix_b, 16, 16, 16, __half, wmma::col_major> bf;
                    wmma::load_matrix_sync(bf, FCsm + (wc*32 + j*16)*FPAD + kt*16, FPAD);
                    #pragma unroll
                    for (int i = 0; i < 2; i++)
                        wmma::mma_sync(accp[i][j], af[i], bf, accp[i][j]);
                }
            }
            #pragma unroll
            for (int i = 0; i < 2; i++)
                #pragma unroll
                for (int j = 0; j < 2; j++)
                    wmma::store_matrix_sync(&pbuf[(wr*32 + i*16)*GPAD + wc*32 + j*16],
                                            accp[i][j], GPAD, wmma::mem_row_major);
        }
        __syncthreads();

        // scatter partials to blocked layout: [dst d][src rk][64][8]
        #pragma unroll
        for (int it = 0; it < 8; it++) {
            int idx = tid + it*NTHREADS;           // 0..2047
            int d = idx >> 7, m = (idx >> 1) & 63, half = idx & 1;
            float4 v = *reinterpret_cast<const float4*>(&pbuf[m*GPAD + d*8 + half*4]);
            *reinterpret_cast<float4*>(
                &fcbase[((d*GCTAS + rk)*MB + m)*8 + half*4]) = v;
        }
        __syncthreads();

        bar_arrive(barp);                // A: h_{t+1} + fc partials published
        tgt += GCTAS;
        bar_wait(barp, tgt);             // (only exposed barrier)

        // ===== finalize own 8 fc cols: reduce 16 contiguous blocks, activate =====
        float yv[2]; int mv[2];
        {
            const float* rbase = &fcbase[rk*GCTAS*MB*8];   // [src][64][8], 32KB contiguous
            #pragma unroll
            for (int it = 0; it < 2; it++) {
                int idx = tid + it*NTHREADS;
                int m = idx >> 3, ff = idx & 7;
                float z = fcbs[ff];
                #pragma unroll
                for (int s = 0; s < GCTAS; s++)
                    z += __ldcg(&rbase[(s*MB + m)*8 + ff]);
                float y = ftanh_(0.5f * z);     // == 2*sigmoid(z) - 1
                g_act[pw][row0+m][HDIM + rk*8 + ff] = __float2half_rn(y);
                yv[it] = y; mv[it] = m;
            }
        }
        __syncthreads();

        if (more) { bar_arrive(barp); tgt += GCTAS; }    // B: inp published

        // out stores overlap barrier-B window
        #pragma unroll
        for (int it = 0; it < 2; it++) {
            int idx = tid + it*NTHREADS;
            int n = rk*8 + (idx & 7);
            out[(TSTEPS-1-t)*BATCH*IDIM + (row0+mv[it])*IDIM + n] = yv[it];
        }

        if (more) {
            // ===== phase1: gates(t+1) h-part (hides barrier B) =====
            #pragma unroll
            for (int i = 0; i < 2; i++)
                #pragma unroll
                for (int j = 0; j < 2; j++)
                    wmma::fill_fragment(acc[i][j], 0.0f);
            mma_chunks(acc, &g_act[pw][0][0], Ast, Wsm, row0, wr, wc, lrow, lseg,
                       0, HCHUNK);

            bar_wait(barp, tgt);         // B: should already be satisfied

            // ===== phase2: inp chunk; publish gsm =====
            mma_chunks(acc, &g_act[pw][0][0], Ast, Wsm, row0, wr, wc, lrow, lseg,
                       HCHUNK, NCHUNK);
            #pragma unroll
            for (int i = 0; i < 2; i++)
                #pragma unroll
                for (int j = 0; j < 2; j++)
                    wmma::store_matrix_sync(&gsm[(wr*32 + i*16)*GPAD + wc*32 + j*16],
                                            acc[i][j], GPAD, wmma::mem_row_major);
            __syncthreads();
        }
    }
}

extern "C" void kernel_launch(void* const* d_in, const int* in_sizes, int n_in,
                              void* d_out, int out_size)
{
    const float* x    = (const float*)d_in[0];
    // d_in[1] = enc_hiddens : unused by the reference recursion
    const float* h0   = (const float*)d_in[2];
    const float* c0   = (const float*)d_in[3];
    const float* W_ih = (const float*)d_in[4];
    const float* W_hh = (const float*)d_in[5];
    const float* b_ih = (const float*)d_in[6];
    const float* b_hh = (const float*)d_in[7];
    const float* fc_W = (const float*)d_in[8];
    const float* fc_b = (const float*)d_in[9];
    float* out = (float*)d_out;

    cudaFuncSetAttribute(decoder_kernel, cudaFuncAttributeMaxDynamicSharedMemorySize, SMEM_BYTES);

    // Reset group-barrier counters every replay (captured memset node)
    void* barp = nullptr;
    cudaGetSymbolAddress(&barp, g_bar);
    cudaMemsetAsync(barp, 0, sizeof(unsigned) * NGROUPS);

    decoder_kernel<<<NCTA, NTHREADS, SMEM_BYTES>>>(x, h0, c0, W_ih, W_hh,
                                                   b_ih, b_hh, fc_W, fc_b, out);
}